// round 4
// baseline (speedup 1.0000x reference)
#include <cuda_runtime.h>
#include <math.h>

#define NEGF (-1000000000.0f)
#define Bn 512
#define Rn 200
#define C1n 32
#define C2n 32
#define C3n 512
#define KHn 8
#define K1n 100
#define K2n 50

// out layout: logp[1024] | wp1[32] | wp2[32] | s1[512*100] | s2[512*50]
#define OUT_WP1 1024
#define OUT_WP2 1056
#define OUT_S1 1088
#define OUT_S2 52288

// ---------------- scratch (device globals; no allocation allowed) ----------------
__device__ float g_wtab1[Rn * Rn * C1n];
__device__ float g_wtab2[Rn * C1n * C2n];
__device__ float g_xt1[Bn * Rn * C1n];
__device__ float g_h1[Bn * Rn * C1n];
__device__ float g_s1[Bn * Rn];
__device__ int   g_perm1[Bn * K1n];
__device__ float g_vals1[Bn * K1n];
__device__ int   g_roi1[Bn * K1n];
__device__ float g_x1[Bn * K1n * C1n];
__device__ float g_wd[Bn * K1n * K1n];
__device__ float g_aaug[Bn * K1n * K1n];
__device__ unsigned char g_maug[Bn * K1n * K1n];
__device__ float g_xt2[Bn * K1n * C2n];
__device__ float g_h2[Bn * K1n * C2n];
__device__ float g_s2[Bn * K1n];
__device__ int   g_perm2[Bn * K2n];
__device__ float g_vals2[Bn * K2n];
__device__ float g_y1[Bn * C2n];
__device__ float g_y2[Bn * C3n];
__device__ float g_stats1[2 * C2n];
__device__ float g_stats2[2 * C3n];

// ---------------- NN weight tables: out[r][j] = b2[j] + sum_k relu(W1[k][r]+b1[k])*W2[j][k]
__global__ void k_tab(const float* __restrict__ W1, const float* __restrict__ b1,
                      const float* __restrict__ W2, const float* __restrict__ b2,
                      int ncols, int which) {
    float* out = which ? g_wtab2 : g_wtab1;
    __shared__ float a[KHn];
    int r = blockIdx.x;
    if (threadIdx.x < KHn) {
        float v = W1[threadIdx.x * Rn + r] + b1[threadIdx.x];
        a[threadIdx.x] = v > 0.f ? v : 0.f;
    }
    __syncthreads();
    for (int j = threadIdx.x; j < ncols; j += blockDim.x) {
        float acc = b2[j];
#pragma unroll
        for (int k = 0; k < KHn; k++) acc = fmaf(a[k], W2[j * KHn + k], acc);
        out[(size_t)r * ncols + j] = acc;
    }
}

// ---------------- xt1[b,n,o] = sum_i x[b,n,i]*wtab1[roi[n]][i][o]
// grid (200, 8), block 256: warp w handles 8 batch rows, lane = o.
__global__ void k_xt1(const float* __restrict__ x, const int* __restrict__ roi) {
    __shared__ float Wsh[Rn * C1n];
    int n = blockIdx.x;
    int r = roi[n];
    const float* wsrc = g_wtab1 + (size_t)r * (Rn * C1n);
    for (int i = threadIdx.x; i < Rn * C1n; i += 256) Wsh[i] = wsrc[i];
    __syncthreads();
    int lane = threadIdx.x & 31, w = threadIdx.x >> 5;
    int b0 = blockIdx.y * 64 + w * 8;
    float acc[8];
#pragma unroll
    for (int k = 0; k < 8; k++) acc[k] = 0.f;
    const float* xb = x + (size_t)b0 * (Rn * Rn) + (size_t)n * Rn;
    for (int i = 0; i < Rn; i++) {
        float wv = Wsh[i * C1n + lane];
#pragma unroll
        for (int k = 0; k < 8; k++)
            acc[k] = fmaf(__ldg(&xb[(size_t)k * (Rn * Rn) + i]), wv, acc[k]);
    }
#pragma unroll
    for (int k = 0; k < 8; k++)
        g_xt1[(size_t)(b0 + k) * (Rn * C1n) + n * C1n + lane] = acc[k];
}

// ---------------- layer-1 softmax attention + h1 + score s1
// grid (512, 7), block 256. 32 rows/block; att stored transposed [j][row], pad 36.
__global__ void k_att1(const float* __restrict__ adj, const float* __restrict__ bias1,
                       const float* __restrict__ wp1) {
    __shared__ __align__(16) float attsh[Rn * 36];
    __shared__ float rowscale[32];
    int b = blockIdx.x;
    int n0 = blockIdx.y * 32;
    int tid = threadIdx.x, lane = tid & 31, w = tid >> 5;

#pragma unroll
    for (int rr = 0; rr < 4; rr++) {
        int rloc = w * 4 + rr;
        int n = n0 + rloc;
        if (n < Rn) {
            const float* arow = adj + ((size_t)b * Rn + n) * Rn;
            float lv[7];
            float m = -INFINITY;
#pragma unroll
            for (int it = 0; it < 7; it++) {
                int j = lane + it * 32;
                float l = -INFINITY;
                if (j < Rn) {
                    float a = arow[j];
                    l = (j == n) ? 1.0f : ((a < 0.1f) ? a : NEGF);
                }
                lv[it] = l;
                m = fmaxf(m, l);
            }
#pragma unroll
            for (int o = 16; o; o >>= 1) m = fmaxf(m, __shfl_xor_sync(0xffffffffu, m, o));
            float s = 0.f;
#pragma unroll
            for (int it = 0; it < 7; it++) {
                int j = lane + it * 32;
                if (j < Rn) {
                    float e = expf(lv[it] - m);
                    attsh[j * 36 + rloc] = e;
                    s += e;
                }
            }
#pragma unroll
            for (int o = 16; o; o >>= 1) s += __shfl_xor_sync(0xffffffffu, s, o);
            if (lane == 0) rowscale[rloc] = 1.0f / s;
        } else {
#pragma unroll
            for (int it = 0; it < 7; it++) {
                int j = lane + it * 32;
                if (j < Rn) attsh[j * 36 + rloc] = 0.f;
            }
        }
    }
    __syncthreads();

    float a0 = 0.f, a1 = 0.f, a2 = 0.f, a3 = 0.f;
    int o = lane;
    const float* xb = g_xt1 + (size_t)b * (Rn * C1n);
    for (int j = 0; j < Rn; j++) {
        float xv = __ldg(&xb[j * C1n + o]);
        float4 av = *reinterpret_cast<const float4*>(&attsh[j * 36 + w * 4]);
        a0 = fmaf(av.x, xv, a0);
        a1 = fmaf(av.y, xv, a1);
        a2 = fmaf(av.z, xv, a2);
        a3 = fmaf(av.w, xv, a3);
    }
    float bo = bias1[o];
    float wv = wp1[o];
    float wn = 0.f;
#pragma unroll
    for (int i = 0; i < C1n; i++) { float t = wp1[i]; wn = fmaf(t, t, wn); }
    float norm = sqrtf(wn);
    float accs[4] = {a0, a1, a2, a3};
#pragma unroll
    for (int rr = 0; rr < 4; rr++) {
        int rloc = w * 4 + rr;
        int n = n0 + rloc;
        if (n < Rn) {
            float h = fmaf(accs[rr], rowscale[rloc], bo);
            g_h1[((size_t)b * Rn + n) * C1n + o] = h;
            float t = h * wv;
#pragma unroll
            for (int off = 16; off; off >>= 1) t += __shfl_xor_sync(0xffffffffu, t, off);
            if (lane == 0) g_s1[b * Rn + n] = 1.f / (1.f + expf(-(t / norm)));
        }
    }
}

// ---------------- exact stable top-k by rank (matches lax.top_k tie semantics)
__global__ void k_topk(int stage, float* __restrict__ outp) {
    const float* s; int N, Ksel; int* perm; float* vals;
    if (stage == 0) { s = g_s1; N = Rn;  Ksel = K1n; perm = g_perm1; vals = g_vals1; }
    else            { s = g_s2; N = K1n; Ksel = K2n; perm = g_perm2; vals = g_vals2; }
    __shared__ float sv[256];
    int b = blockIdx.x, tid = threadIdx.x;
    sv[tid] = (tid < N) ? s[b * N + tid] : -INFINITY;
    __syncthreads();
    if (tid < N) {
        float v = sv[tid];
        int rank = 0;
        for (int j = 0; j < N; j++) {
            float u = sv[j];
            rank += (u > v) || (u == v && j < tid);
        }
        if (rank < Ksel) {
            perm[b * Ksel + rank] = tid;
            vals[b * Ksel + rank] = v;
            outp[b * Ksel + rank] = 1.f / (1.f + expf(-v));  // sigmoid(vals)
        }
    }
}

// ---------------- gather x1, roi1; build wd (diag 1, masked adj else 0)
__global__ void k_gather1(const float* __restrict__ adj, const int* __restrict__ roi) {
    __shared__ int permsh[K1n];
    __shared__ float valsh[K1n];
    int b = blockIdx.x, tid = threadIdx.x;
    if (tid < K1n) {
        int p = g_perm1[b * K1n + tid];
        permsh[tid] = p;
        valsh[tid] = g_vals1[b * K1n + tid];
        g_roi1[b * K1n + tid] = roi[p];
    }
    __syncthreads();
    for (int idx = tid; idx < K1n * C1n; idx += 256) {
        int p = idx >> 5, o = idx & 31;
        g_x1[(size_t)b * (K1n * C1n) + idx] =
            g_h1[((size_t)b * Rn + permsh[p]) * C1n + o] * valsh[p];
    }
    for (int idx = tid; idx < K1n * K1n; idx += 256) {
        int i = idx / K1n, k = idx - i * K1n;
        float outv;
        if (i == k) outv = 1.0f;
        else {
            float a = adj[((size_t)b * Rn + permsh[i]) * Rn + permsh[k]];
            outv = (a < 0.1f) ? a : 0.0f;
        }
        g_wd[(size_t)b * (K1n * K1n) + idx] = outv;
    }
}

// ---------------- a2 = wd@wd; m2 = (a2 != 0) & ~eye; a2 diag forced 0
// grid (512, 7), block 128; 16 i-rows per block via transposed shared tile.
__global__ void k_aug() {
    __shared__ __align__(16) float wdIT[K1n * 16];  // [k][i]
    int b = blockIdx.x;
    int itile = blockIdx.y * 16;
    int ni = min(16, K1n - itile);
    int tid = threadIdx.x;
    const float* wdb = g_wd + (size_t)b * (K1n * K1n);
    for (int idx = tid; idx < 16 * K1n; idx += 128) {
        int i = idx / K1n, k = idx - i * K1n;
        wdIT[k * 16 + i] = (i < ni) ? wdb[(itile + i) * K1n + k] : 0.f;
    }
    __syncthreads();
    int j = tid;
    if (j < K1n) {
        float acc[16];
#pragma unroll
        for (int i = 0; i < 16; i++) acc[i] = 0.f;
        for (int k = 0; k < K1n; k++) {
            float wkj = __ldg(&wdb[k * K1n + j]);
            const float4* wp4 = reinterpret_cast<const float4*>(&wdIT[k * 16]);
            float4 w0 = wp4[0], w1 = wp4[1], w2 = wp4[2], w3 = wp4[3];
            acc[0]  = fmaf(w0.x, wkj, acc[0]);
            acc[1]  = fmaf(w0.y, wkj, acc[1]);
            acc[2]  = fmaf(w0.z, wkj, acc[2]);
            acc[3]  = fmaf(w0.w, wkj, acc[3]);
            acc[4]  = fmaf(w1.x, wkj, acc[4]);
            acc[5]  = fmaf(w1.y, wkj, acc[5]);
            acc[6]  = fmaf(w1.z, wkj, acc[6]);
            acc[7]  = fmaf(w1.w, wkj, acc[7]);
            acc[8]  = fmaf(w2.x, wkj, acc[8]);
            acc[9]  = fmaf(w2.y, wkj, acc[9]);
            acc[10] = fmaf(w2.z, wkj, acc[10]);
            acc[11] = fmaf(w2.w, wkj, acc[11]);
            acc[12] = fmaf(w3.x, wkj, acc[12]);
            acc[13] = fmaf(w3.y, wkj, acc[13]);
            acc[14] = fmaf(w3.z, wkj, acc[14]);
            acc[15] = fmaf(w3.w, wkj, acc[15]);
        }
#pragma unroll
        for (int i = 0; i < 16; i++) {
            if (i < ni) {
                int gi = itile + i;
                float v = acc[i];
                bool diag = (gi == j);
                g_aaug[(size_t)b * (K1n * K1n) + gi * K1n + j] = diag ? 0.f : v;
                g_maug[(size_t)b * (K1n * K1n) + gi * K1n + j] =
                    (!diag && v != 0.f) ? (unsigned char)1 : (unsigned char)0;
            }
        }
    }
}

// ---------------- xt2[b,p,o] = sum_i x1[b,p,i]*wtab2[roi1[b,p]][i][o]
__global__ void k_xt2() {
    int b = blockIdx.x;
    int lane = threadIdx.x & 31, w = threadIdx.x >> 5;
    int p = blockIdx.y * 8 + w;
    if (p >= K1n) return;
    int r = g_roi1[b * K1n + p];
    const float* xr = g_x1 + ((size_t)b * K1n + p) * C1n;
    const float* wt = g_wtab2 + (size_t)r * (C1n * C2n);
    float acc = 0.f;
#pragma unroll
    for (int i = 0; i < C1n; i++) acc = fmaf(__ldg(&xr[i]), __ldg(&wt[i * C2n + lane]), acc);
    g_xt2[((size_t)b * K1n + p) * C2n + lane] = acc;
}

// ---------------- layer-2 attention + h2 + score s2. grid (512, 4), block 256.
__global__ void k_att2(const float* __restrict__ bias2, const float* __restrict__ wp2) {
    __shared__ float xtsh[K1n * C2n];
    __shared__ __align__(16) float attsh[K1n * 36];
    __shared__ float rowscale[32];
    int b = blockIdx.x;
    int n0 = blockIdx.y * 32;
    int tid = threadIdx.x, lane = tid & 31, w = tid >> 5;
    const float* xb = g_xt2 + (size_t)b * (K1n * C2n);
    for (int i = tid; i < K1n * C2n; i += 256) xtsh[i] = xb[i];
    const float* ab = g_aaug + (size_t)b * (K1n * K1n);
    const unsigned char* mb = g_maug + (size_t)b * (K1n * K1n);

#pragma unroll
    for (int rr = 0; rr < 4; rr++) {
        int rloc = w * 4 + rr;
        int n = n0 + rloc;
        if (n < K1n) {
            float lv[4];
            float m = -INFINITY;
#pragma unroll
            for (int it = 0; it < 4; it++) {
                int j = lane + it * 32;
                float l = -INFINITY;
                if (j < K1n)
                    l = (j == n) ? 1.0f : (mb[n * K1n + j] ? ab[n * K1n + j] : NEGF);
                lv[it] = l;
                m = fmaxf(m, l);
            }
#pragma unroll
            for (int o = 16; o; o >>= 1) m = fmaxf(m, __shfl_xor_sync(0xffffffffu, m, o));
            float s = 0.f;
#pragma unroll
            for (int it = 0; it < 4; it++) {
                int j = lane + it * 32;
                if (j < K1n) {
                    float e = expf(lv[it] - m);
                    attsh[j * 36 + rloc] = e;
                    s += e;
                }
            }
#pragma unroll
            for (int o = 16; o; o >>= 1) s += __shfl_xor_sync(0xffffffffu, s, o);
            if (lane == 0) rowscale[rloc] = 1.0f / s;
        } else {
#pragma unroll
            for (int it = 0; it < 4; it++) {
                int j = lane + it * 32;
                if (j < K1n) attsh[j * 36 + rloc] = 0.f;
            }
        }
    }
    __syncthreads();

    float a0 = 0.f, a1 = 0.f, a2 = 0.f, a3 = 0.f;
    int o = lane;
    for (int j = 0; j < K1n; j++) {
        float xv = xtsh[j * C2n + o];
        float4 av = *reinterpret_cast<const float4*>(&attsh[j * 36 + w * 4]);
        a0 = fmaf(av.x, xv, a0);
        a1 = fmaf(av.y, xv, a1);
        a2 = fmaf(av.z, xv, a2);
        a3 = fmaf(av.w, xv, a3);
    }
    float bo = bias2[o];
    float wv = wp2[o];
    float wn = 0.f;
#pragma unroll
    for (int i = 0; i < C2n; i++) { float t = wp2[i]; wn = fmaf(t, t, wn); }
    float norm = sqrtf(wn);
    float accs[4] = {a0, a1, a2, a3};
#pragma unroll
    for (int rr = 0; rr < 4; rr++) {
        int rloc = w * 4 + rr;
        int n = n0 + rloc;
        if (n < K1n) {
            float h = fmaf(accs[rr], rowscale[rloc], bo);
            g_h2[((size_t)b * K1n + n) * C2n + o] = h;
            float t = h * wv;
#pragma unroll
            for (int off = 16; off; off >>= 1) t += __shfl_xor_sync(0xffffffffu, t, off);
            if (lane == 0) g_s2[b * K1n + n] = 1.f / (1.f + expf(-(t / norm)));
        }
    }
}

// ---------------- feature concat + MLP layer 1 (pre-BN, post-leaky)
__global__ void k_feat(const float* __restrict__ Wm1, const float* __restrict__ bm1) {
    __shared__ float red[8 * 32];
    __shared__ float red2[8 * 32];
    __shared__ float featsh[128];
    int b = blockIdx.x, tid = threadIdx.x, lane = tid & 31, w = tid >> 5;

    const float* x1b = g_x1 + (size_t)b * (K1n * C1n);
    float mx = -INFINITY, sm = 0.f;
    for (int p = w; p < K1n; p += 8) {
        float v = x1b[p * C1n + lane];
        mx = fmaxf(mx, v);
        sm += v;
    }
    red[w * 32 + lane] = mx;
    red2[w * 32 + lane] = sm;
    __syncthreads();
    if (w == 0) {
        float m = red[lane], s = red2[lane];
#pragma unroll
        for (int q = 1; q < 8; q++) { m = fmaxf(m, red[q * 32 + lane]); s += red2[q * 32 + lane]; }
        featsh[lane] = m;
        featsh[32 + lane] = s / (float)K1n;
    }
    __syncthreads();

    const float* h2b = g_h2 + (size_t)b * (K1n * C2n);
    mx = -INFINITY;
    sm = 0.f;
    for (int p = w; p < K2n; p += 8) {
        int pp = g_perm2[b * K2n + p];
        float v = h2b[pp * C2n + lane] * g_vals2[b * K2n + p];
        mx = fmaxf(mx, v);
        sm += v;
    }
    red[w * 32 + lane] = mx;
    red2[w * 32 + lane] = sm;
    __syncthreads();
    if (w == 0) {
        float m = red[lane], s = red2[lane];
#pragma unroll
        for (int q = 1; q < 8; q++) { m = fmaxf(m, red[q * 32 + lane]); s += red2[q * 32 + lane]; }
        featsh[64 + lane] = m;
        featsh[96 + lane] = s / (float)K2n;
    }
    __syncthreads();

    if (tid < C2n) {
        float acc = bm1[tid];
        const float* wrow = Wm1 + tid * 128;
#pragma unroll
        for (int f = 0; f < 128; f++) acc = fmaf(featsh[f], wrow[f], acc);
        g_y1[b * C2n + tid] = acc > 0.f ? acc : 0.01f * acc;
    }
}

// ---------------- batch-norm stats (two-pass). block=512 (one thread per row).
__global__ void k_bn(int stage) {
    const float* y = stage ? g_y2 : g_y1;
    int ncols = stage ? C3n : C2n;
    float* stats = stage ? g_stats2 : g_stats1;
    __shared__ float sh[512];
    __shared__ float mu_s;
    int c = blockIdx.x, tid = threadIdx.x;
    float v = y[(size_t)tid * ncols + c];
    sh[tid] = v;
    __syncthreads();
    for (int s = 256; s; s >>= 1) {
        if (tid < s) sh[tid] += sh[tid + s];
        __syncthreads();
    }
    if (tid == 0) mu_s = sh[0] * (1.0f / 512.0f);
    __syncthreads();
    float d = v - mu_s;
    sh[tid] = d * d;
    __syncthreads();
    for (int s = 256; s; s >>= 1) {
        if (tid < s) sh[tid] += sh[tid + s];
        __syncthreads();
    }
    if (tid == 0) {
        stats[c] = mu_s;
        stats[ncols + c] = rsqrtf(sh[0] * (1.0f / 512.0f) + 1e-5f);
    }
}

// ---------------- MLP layer 2: normalize y1 (g1,be1), linear Wm2, leaky -> g_y2
__global__ void k_mlp2(const float* __restrict__ Wm2, const float* __restrict__ bm2,
                       const float* __restrict__ g1, const float* __restrict__ be1) {
    __shared__ float ynorm[C2n];
    int b = blockIdx.x, tid = threadIdx.x;
    if (tid < C2n) {
        float v = g_y1[b * C2n + tid];
        ynorm[tid] = fmaf(g1[tid] * (v - g_stats1[tid]), g_stats1[C2n + tid], be1[tid]);
    }
    __syncthreads();
    float acc = bm2[tid];
    const float* wrow = Wm2 + tid * C2n;
#pragma unroll
    for (int i = 0; i < C2n; i++) acc = fmaf(ynorm[i], wrow[i], acc);
    g_y2[b * C3n + tid] = acc > 0.f ? acc : 0.01f * acc;
}

// ---------------- head: normalize y2 (g2,be2), logits = z@Ws.T + bs, log_softmax
__global__ void k_head(const float* __restrict__ g2, const float* __restrict__ be2,
                       const float* __restrict__ Ws, const float* __restrict__ bs,
                       float* __restrict__ out) {
    __shared__ float p0sh[512];
    __shared__ float p1sh[512];
    int b = blockIdx.x, tid = threadIdx.x;
    float v = g_y2[b * C3n + tid];
    float z = fmaf(g2[tid] * (v - g_stats2[tid]), g_stats2[C3n + tid], be2[tid]);
    p0sh[tid] = z * Ws[tid];
    p1sh[tid] = z * Ws[C3n + tid];
    __syncthreads();
    for (int s = 256; s; s >>= 1) {
        if (tid < s) { p0sh[tid] += p0sh[tid + s]; p1sh[tid] += p1sh[tid + s]; }
        __syncthreads();
    }
    if (tid == 0) {
        float l0 = p0sh[0] + bs[0];
        float l1 = p1sh[0] + bs[1];
        float m = fmaxf(l0, l1);
        float lse = m + logf(expf(l0 - m) + expf(l1 - m));
        out[b * 2 + 0] = l0 - lse;
        out[b * 2 + 1] = l1 - lse;
    }
}

// ---------------- passthrough copies
__global__ void k_copy(const float* __restrict__ wp1, const float* __restrict__ wp2,
                       float* __restrict__ out) {
    int t = threadIdx.x;
    if (t < 32) out[OUT_WP1 + t] = wp1[t];
    else if (t < 64) out[OUT_WP2 + (t - 32)] = wp2[t - 32];
}

extern "C" void kernel_launch(void* const* d_in, const int* in_sizes, int n_in,
                              void* d_out, int out_size) {
    const float* x     = (const float*)d_in[0];
    const float* adj   = (const float*)d_in[1];
    const int*   roi   = (const int*)d_in[2];
    const float* W1a   = (const float*)d_in[3];
    const float* b1a   = (const float*)d_in[4];
    const float* W2a   = (const float*)d_in[5];
    const float* b2a   = (const float*)d_in[6];
    const float* bias1 = (const float*)d_in[7];
    const float* W1b   = (const float*)d_in[8];
    const float* b1b   = (const float*)d_in[9];
    const float* W2b   = (const float*)d_in[10];
    const float* b2b   = (const float*)d_in[11];
    const float* bias2 = (const float*)d_in[12];
    const float* wp1   = (const float*)d_in[13];
    const float* wp2   = (const float*)d_in[14];
    const float* Wm1   = (const float*)d_in[15];
    const float* bm1   = (const float*)d_in[16];
    const float* g1    = (const float*)d_in[17];
    const float* be1   = (const float*)d_in[18];
    const float* Wm2   = (const float*)d_in[19];
    const float* bm2   = (const float*)d_in[20];
    const float* g2    = (const float*)d_in[21];
    const float* be2   = (const float*)d_in[22];
    const float* Ws    = (const float*)d_in[23];
    const float* bs    = (const float*)d_in[24];
    float* out = (float*)d_out;

    k_tab<<<Rn, 256>>>(W1a, b1a, W2a, b2a, Rn * C1n, 0);
    k_tab<<<Rn, 256>>>(W1b, b1b, W2b, b2b, C1n * C2n, 1);
    k_xt1<<<dim3(Rn, 8), 256>>>(x, roi);
    k_att1<<<dim3(Bn, 7), 256>>>(adj, bias1, wp1);
    k_topk<<<Bn, 256>>>(0, out + OUT_S1);
    k_gather1<<<Bn, 256>>>(adj, roi);
    k_aug<<<dim3(Bn, 7), 128>>>();
    k_xt2<<<dim3(Bn, 13), 256>>>();
    k_att2<<<dim3(Bn, 4), 256>>>(bias2, wp2);
    k_topk<<<Bn, 256>>>(1, out + OUT_S2);
    k_feat<<<Bn, 256>>>(Wm1, bm1);
    k_bn<<<C2n, 512>>>(0);
    k_mlp2<<<Bn, C3n>>>(Wm2, bm2, g1, be1);
    k_bn<<<C3n, 512>>>(1);
    k_head<<<Bn, C3n>>>(g2, be2, Ws, bs, out);
    k_copy<<<1, 64>>>(wp1, wp2, out);
}

// round 9
// speedup vs baseline: 1.2329x; 1.2329x over previous
#include <cuda_runtime.h>
#include <math.h>

#define NEGF (-1000000000.0f)
#define Bn 512
#define Rn 200
#define C1n 32
#define C2n 32
#define C3n 512
#define KHn 8
#define K1n 100
#define K2n 50
#define FULLM 0xffffffffu

// out layout: logp[1024] | wp1[32] | wp2[32] | s1[512*100] | s2[512*50]
#define OUT_WP1 1024
#define OUT_WP2 1056
#define OUT_S1 1088
#define OUT_S2 52288

// ---------------- scratch ----------------
__device__ float g_wtab1[Rn * Rn * C1n];
__device__ float g_wtab2[Rn * C1n * C2n];
__device__ float g_xt1[Bn * Rn * C1n];
__device__ float g_h1[Bn * Rn * C1n];
__device__ float g_s1[Bn * Rn];
__device__ int   g_perm1[Bn * K1n];
__device__ float g_vals1[Bn * K1n];
__device__ int   g_roi1[Bn * K1n];
__device__ float g_x1[Bn * K1n * C1n];
__device__ float g_wd[Bn * K1n * K1n];
__device__ float g_aaug[Bn * K1n * K1n];
__device__ unsigned char g_maug[Bn * K1n * K1n];
__device__ float g_xt2[Bn * K1n * C2n];
__device__ float g_h2[Bn * K1n * C2n];
__device__ float g_s2[Bn * K1n];
__device__ int   g_perm2[Bn * K2n];
__device__ float g_vals2[Bn * K2n];
__device__ float g_y1[Bn * C2n];
__device__ float g_y2[Bn * C3n];
__device__ float g_stats1[2 * C2n];
__device__ float g_stats2[2 * C3n];

// ---------------- NN weight tables ----------------
__global__ void k_tab(const float* __restrict__ W1, const float* __restrict__ b1,
                      const float* __restrict__ W2, const float* __restrict__ b2,
                      int ncols, int which) {
    float* out = which ? g_wtab2 : g_wtab1;
    __shared__ float a[KHn];
    int r = blockIdx.x;
    if (threadIdx.x < KHn) {
        float v = W1[threadIdx.x * Rn + r] + b1[threadIdx.x];
        a[threadIdx.x] = v > 0.f ? v : 0.f;
    }
    __syncthreads();
    for (int j = threadIdx.x; j < ncols; j += blockDim.x) {
        float acc = b2[j];
#pragma unroll
        for (int k = 0; k < KHn; k++) acc = fmaf(a[k], W2[j * KHn + k], acc);
        out[(size_t)r * ncols + j] = acc;
    }
}

// ---------------- xt1[b,n,o] = sum_i x[b,n,i]*wtab1[roi[n]][i][o]
// grid (200, 8), block 256: warp w handles 8 batch rows, lane = o.
// Inner loop unrolled by 4 i's with float4 broadcast loads of x.
__global__ void k_xt1(const float* __restrict__ x, const int* __restrict__ roi) {
    __shared__ float Wsh[Rn * C1n];
    int n = blockIdx.x;
    int r = roi[n];
    const float* wsrc = g_wtab1 + (size_t)r * (Rn * C1n);
    for (int i = threadIdx.x; i < Rn * C1n; i += 256) Wsh[i] = wsrc[i];
    __syncthreads();
    int lane = threadIdx.x & 31, w = threadIdx.x >> 5;
    int b0 = blockIdx.y * 64 + w * 8;
    float acc[8];
#pragma unroll
    for (int k = 0; k < 8; k++) acc[k] = 0.f;
    const float* xb = x + (size_t)b0 * (Rn * Rn) + (size_t)n * Rn;
    for (int i0 = 0; i0 < Rn; i0 += 4) {
        float4 xv[8];
#pragma unroll
        for (int k = 0; k < 8; k++)
            xv[k] = *reinterpret_cast<const float4*>(&xb[(size_t)k * (Rn * Rn) + i0]);
#pragma unroll
        for (int d = 0; d < 4; d++) {
            float wv = Wsh[(i0 + d) * C1n + lane];
#pragma unroll
            for (int k = 0; k < 8; k++) {
                const float* xc = reinterpret_cast<const float*>(&xv[k]);
                acc[k] = fmaf(xc[d], wv, acc[k]);
            }
        }
    }
#pragma unroll
    for (int k = 0; k < 8; k++)
        g_xt1[(size_t)(b0 + k) * (Rn * C1n) + n * C1n + lane] = acc[k];
}

// ---------------- layer-1 attention, SPARSE (mask keeps ~10% of edges).
// Row max is ALWAYS the diag logit 1.0 (edges < 0.1 < 1.0, masked = NEG).
// So att_j = exp(a_j-1)/Z with Z = 1 + sum(exp(a_j-1)); zeros skipped exactly.
// grid (512, 25), block 256: one warp per row n, lane = channel o.
__global__ void k_att1(const float* __restrict__ adj, const float* __restrict__ bias1,
                       const float* __restrict__ wp1) {
    int b = blockIdx.x;
    int lane = threadIdx.x & 31, w = threadIdx.x >> 5;
    int n = blockIdx.y * 8 + w;
    const float* arow = adj + ((size_t)b * Rn + n) * Rn;
    const float* xb = g_xt1 + (size_t)b * (Rn * C1n);

    float acc = 0.f;
    float zpart = 0.f;
#pragma unroll
    for (int it = 0; it < 7; it++) {
        int j = it * 32 + lane;
        float a = (j < Rn) ? __ldg(&arow[j]) : 1.0f;
        bool isedge = (j < Rn) && (j != n) && (a < 0.1f);
        float e = isedge ? expf(a - 1.0f) : 0.f;
        zpart += e;
        unsigned bits = __ballot_sync(FULLM, isedge);
        while (bits) {
            int src = __ffs(bits) - 1;
            bits &= bits - 1;
            float we = __shfl_sync(FULLM, e, src);
            int jj = it * 32 + src;
            acc = fmaf(we, __ldg(&xb[jj * C1n + lane]), acc);
        }
    }
    float Z = zpart;
#pragma unroll
    for (int o = 16; o; o >>= 1) Z += __shfl_xor_sync(FULLM, Z, o);
    Z += 1.0f;  // diagonal: exp(1-1) = 1
    float invZ = 1.0f / Z;
    float h = fmaf(acc + __ldg(&xb[n * C1n + lane]), invZ, bias1[lane]);
    g_h1[((size_t)b * Rn + n) * C1n + lane] = h;

    float wv = wp1[lane];
    float t = h * wv;
    float wn = wv * wv;
#pragma unroll
    for (int o = 16; o; o >>= 1) {
        t += __shfl_xor_sync(FULLM, t, o);
        wn += __shfl_xor_sync(FULLM, wn, o);
    }
    if (lane == 0) {
        float norm = sqrtf(wn);
        g_s1[b * Rn + n] = 1.f / (1.f + expf(-(t / norm)));
    }
}

// ---------------- exact stable top-k by rank (matches lax.top_k tie semantics)
__global__ void k_topk(int stage, float* __restrict__ outp) {
    const float* s; int N, Ksel; int* perm; float* vals;
    if (stage == 0) { s = g_s1; N = Rn;  Ksel = K1n; perm = g_perm1; vals = g_vals1; }
    else            { s = g_s2; N = K1n; Ksel = K2n; perm = g_perm2; vals = g_vals2; }
    __shared__ float sv[256];
    int b = blockIdx.x, tid = threadIdx.x;
    sv[tid] = (tid < N) ? s[b * N + tid] : -INFINITY;
    __syncthreads();
    if (tid < N) {
        float v = sv[tid];
        int rank = 0;
        for (int j = 0; j < N; j++) {
            float u = sv[j];
            rank += (u > v) || (u == v && j < tid);
        }
        if (rank < Ksel) {
            perm[b * Ksel + rank] = tid;
            vals[b * Ksel + rank] = v;
            outp[b * Ksel + rank] = 1.f / (1.f + expf(-v));  // sigmoid(vals)
        }
    }
}

// ---------------- gather x1, roi1; build wd (diag 1, masked adj else 0)
__global__ void k_gather1(const float* __restrict__ adj, const int* __restrict__ roi) {
    __shared__ int permsh[K1n];
    __shared__ float valsh[K1n];
    int b = blockIdx.x, tid = threadIdx.x;
    if (tid < K1n) {
        int p = g_perm1[b * K1n + tid];
        permsh[tid] = p;
        valsh[tid] = g_vals1[b * K1n + tid];
        g_roi1[b * K1n + tid] = roi[p];
    }
    __syncthreads();
    for (int idx = tid; idx < K1n * C1n; idx += 256) {
        int p = idx >> 5, o = idx & 31;
        g_x1[(size_t)b * (K1n * C1n) + idx] =
            g_h1[((size_t)b * Rn + permsh[p]) * C1n + o] * valsh[p];
    }
    for (int idx = tid; idx < K1n * K1n; idx += 256) {
        int i = idx / K1n, k = idx - i * K1n;
        float outv;
        if (i == k) outv = 1.0f;
        else {
            float a = adj[((size_t)b * Rn + permsh[i]) * Rn + permsh[k]];
            outv = (a < 0.1f) ? a : 0.0f;
        }
        g_wd[(size_t)b * (K1n * K1n) + idx] = outv;
    }
}

// ---------------- a2 = wd@wd SPARSE (wd rows ~11/100 nonzero, incl. diag).
// grid (512, 13), block 256: one warp per output row i, lane covers j in 4 chunks.
// Skipped terms are exact zeros -> rounding identical to dense k-ascending sum.
__global__ void k_aug() {
    int b = blockIdx.x;
    int lane = threadIdx.x & 31, w = threadIdx.x >> 5;
    int i = blockIdx.y * 8 + w;
    if (i >= K1n) return;
    const float* wdb = g_wd + (size_t)b * (K1n * K1n);
    const float* ri = wdb + i * K1n;
    float r[4];
    float acc[4] = {0.f, 0.f, 0.f, 0.f};
#pragma unroll
    for (int c = 0; c < 4; c++) {
        int j = c * 32 + lane;
        r[c] = (j < K1n) ? __ldg(&ri[j]) : 0.f;
    }
#pragma unroll
    for (int c = 0; c < 4; c++) {
        unsigned bits = __ballot_sync(FULLM, r[c] != 0.f);
        while (bits) {
            int src = __ffs(bits) - 1;
            bits &= bits - 1;
            float wik = __shfl_sync(FULLM, r[c], src);
            int k = c * 32 + src;
            const float* rk = wdb + k * K1n;
#pragma unroll
            for (int cc = 0; cc < 4; cc++) {
                int j = cc * 32 + lane;
                if (j < K1n) acc[cc] = fmaf(wik, __ldg(&rk[j]), acc[cc]);
            }
        }
    }
#pragma unroll
    for (int cc = 0; cc < 4; cc++) {
        int j = cc * 32 + lane;
        if (j < K1n) {
            float v = acc[cc];
            bool diag = (j == i);
            g_aaug[(size_t)b * (K1n * K1n) + i * K1n + j] = diag ? 0.f : v;
            g_maug[(size_t)b * (K1n * K1n) + i * K1n + j] =
                (!diag && v != 0.f) ? (unsigned char)1 : (unsigned char)0;
        }
    }
}

// ---------------- xt2[b,p,o] = sum_i x1[b,p,i]*wtab2[roi1[b,p]][i][o]
__global__ void k_xt2() {
    int b = blockIdx.x;
    int lane = threadIdx.x & 31, w = threadIdx.x >> 5;
    int p = blockIdx.y * 8 + w;
    if (p >= K1n) return;
    int r = g_roi1[b * K1n + p];
    const float* xr = g_x1 + ((size_t)b * K1n + p) * C1n;
    const float* wt = g_wtab2 + (size_t)r * (C1n * C2n);
    float acc = 0.f;
#pragma unroll
    for (int i = 0; i < C1n; i++) acc = fmaf(__ldg(&xr[i]), __ldg(&wt[i * C2n + lane]), acc);
    g_xt2[((size_t)b * K1n + p) * C2n + lane] = acc;
}

// ---------------- layer-2 attention + h2 + score s2. grid (512, 4), block 256.
__global__ void k_att2(const float* __restrict__ bias2, const float* __restrict__ wp2) {
    __shared__ float xtsh[K1n * C2n];
    __shared__ __align__(16) float attsh[K1n * 36];
    __shared__ float rowscale[32];
    int b = blockIdx.x;
    int n0 = blockIdx.y * 32;
    int tid = threadIdx.x, lane = tid & 31, w = tid >> 5;
    const float* xb = g_xt2 + (size_t)b * (K1n * C2n);
    for (int i = tid; i < K1n * C2n; i += 256) xtsh[i] = xb[i];
    const float* ab = g_aaug + (size_t)b * (K1n * K1n);
    const unsigned char* mb = g_maug + (size_t)b * (K1n * K1n);

#pragma unroll
    for (int rr = 0; rr < 4; rr++) {
        int rloc = w * 4 + rr;
        int n = n0 + rloc;
        if (n < K1n) {
            float lv[4];
            float m = -INFINITY;
#pragma unroll
            for (int it = 0; it < 4; it++) {
                int j = lane + it * 32;
                float l = -INFINITY;
                if (j < K1n)
                    l = (j == n) ? 1.0f : (mb[n * K1n + j] ? ab[n * K1n + j] : NEGF);
                lv[it] = l;
                m = fmaxf(m, l);
            }
#pragma unroll
            for (int o = 16; o; o >>= 1) m = fmaxf(m, __shfl_xor_sync(FULLM, m, o));
            float s = 0.f;
#pragma unroll
            for (int it = 0; it < 4; it++) {
                int j = lane + it * 32;
                if (j < K1n) {
                    float e = expf(lv[it] - m);
                    attsh[j * 36 + rloc] = e;
                    s += e;
                }
            }
#pragma unroll
            for (int o = 16; o; o >>= 1) s += __shfl_xor_sync(FULLM, s, o);
            if (lane == 0) rowscale[rloc] = 1.0f / s;
        } else {
#pragma unroll
            for (int it = 0; it < 4; it++) {
                int j = lane + it * 32;
                if (j < K1n) attsh[j * 36 + rloc] = 0.f;
            }
        }
    }
    __syncthreads();

    float a0 = 0.f, a1 = 0.f, a2 = 0.f, a3 = 0.f;
    int o = lane;
    for (int j = 0; j < K1n; j++) {
        float xv = xtsh[j * C2n + o];
        float4 av = *reinterpret_cast<const float4*>(&attsh[j * 36 + w * 4]);
        a0 = fmaf(av.x, xv, a0);
        a1 = fmaf(av.y, xv, a1);
        a2 = fmaf(av.z, xv, a2);
        a3 = fmaf(av.w, xv, a3);
    }
    float bo = bias2[o];
    float wv = wp2[o];
    float wn = 0.f;
#pragma unroll
    for (int i = 0; i < C2n; i++) { float t = wp2[i]; wn = fmaf(t, t, wn); }
    float norm = sqrtf(wn);
    float accs[4] = {a0, a1, a2, a3};
#pragma unroll
    for (int rr = 0; rr < 4; rr++) {
        int rloc = w * 4 + rr;
        int n = n0 + rloc;
        if (n < K1n) {
            float h = fmaf(accs[rr], rowscale[rloc], bo);
            g_h2[((size_t)b * K1n + n) * C2n + o] = h;
            float t = h * wv;
#pragma unroll
            for (int off = 16; off; off >>= 1) t += __shfl_xor_sync(FULLM, t, off);
            if (lane == 0) g_s2[b * K1n + n] = 1.f / (1.f + expf(-(t / norm)));
        }
    }
}

// ---------------- feature concat + MLP layer 1 (pre-BN, post-leaky)
__global__ void k_feat(const float* __restrict__ Wm1, const float* __restrict__ bm1) {
    __shared__ float red[8 * 32];
    __shared__ float red2[8 * 32];
    __shared__ float featsh[128];
    int b = blockIdx.x, tid = threadIdx.x, lane = tid & 31, w = tid >> 5;

    const float* x1b = g_x1 + (size_t)b * (K1n * C1n);
    float mx = -INFINITY, sm = 0.f;
    for (int p = w; p < K1n; p += 8) {
        float v = x1b[p * C1n + lane];
        mx = fmaxf(mx, v);
        sm += v;
    }
    red[w * 32 + lane] = mx;
    red2[w * 32 + lane] = sm;
    __syncthreads();
    if (w == 0) {
        float m = red[lane], s = red2[lane];
#pragma unroll
        for (int q = 1; q < 8; q++) { m = fmaxf(m, red[q * 32 + lane]); s += red2[q * 32 + lane]; }
        featsh[lane] = m;
        featsh[32 + lane] = s / (float)K1n;
    }
    __syncthreads();

    const float* h2b = g_h2 + (size_t)b * (K1n * C2n);
    mx = -INFINITY;
    sm = 0.f;
    for (int p = w; p < K2n; p += 8) {
        int pp = g_perm2[b * K2n + p];
        float v = h2b[pp * C2n + lane] * g_vals2[b * K2n + p];
        mx = fmaxf(mx, v);
        sm += v;
    }
    red[w * 32 + lane] = mx;
    red2[w * 32 + lane] = sm;
    __syncthreads();
    if (w == 0) {
        float m = red[lane], s = red2[lane];
#pragma unroll
        for (int q = 1; q < 8; q++) { m = fmaxf(m, red[q * 32 + lane]); s += red2[q * 32 + lane]; }
        featsh[64 + lane] = m;
        featsh[96 + lane] = s / (float)K2n;
    }
    __syncthreads();

    if (tid < C2n) {
        float acc = bm1[tid];
        const float* wrow = Wm1 + tid * 128;
#pragma unroll
        for (int f = 0; f < 128; f++) acc = fmaf(featsh[f], wrow[f], acc);
        g_y1[b * C2n + tid] = acc > 0.f ? acc : 0.01f * acc;
    }
}

// ---------------- batch-norm stats (two-pass). block=512 (one thread per row).
__global__ void k_bn(int stage) {
    const float* y = stage ? g_y2 : g_y1;
    int ncols = stage ? C3n : C2n;
    float* stats = stage ? g_stats2 : g_stats1;
    __shared__ float sh[512];
    __shared__ float mu_s;
    int c = blockIdx.x, tid = threadIdx.x;
    float v = y[(size_t)tid * ncols + c];
    sh[tid] = v;
    __syncthreads();
    for (int s = 256; s; s >>= 1) {
        if (tid < s) sh[tid] += sh[tid + s];
        __syncthreads();
    }
    if (tid == 0) mu_s = sh[0] * (1.0f / 512.0f);
    __syncthreads();
    float d = v - mu_s;
    sh[tid] = d * d;
    __syncthreads();
    for (int s = 256; s; s >>= 1) {
        if (tid < s) sh[tid] += sh[tid + s];
        __syncthreads();
    }
    if (tid == 0) {
        stats[c] = mu_s;
        stats[ncols + c] = rsqrtf(sh[0] * (1.0f / 512.0f) + 1e-5f);
    }
}

// ---------------- MLP layer 2
__global__ void k_mlp2(const float* __restrict__ Wm2, const float* __restrict__ bm2,
                       const float* __restrict__ g1, const float* __restrict__ be1) {
    __shared__ float ynorm[C2n];
    int b = blockIdx.x, tid = threadIdx.x;
    if (tid < C2n) {
        float v = g_y1[b * C2n + tid];
        ynorm[tid] = fmaf(g1[tid] * (v - g_stats1[tid]), g_stats1[C2n + tid], be1[tid]);
    }
    __syncthreads();
    float acc = bm2[tid];
    const float* wrow = Wm2 + tid * C2n;
#pragma unroll
    for (int i = 0; i < C2n; i++) acc = fmaf(ynorm[i], wrow[i], acc);
    g_y2[b * C3n + tid] = acc > 0.f ? acc : 0.01f * acc;
}

// ---------------- head
__global__ void k_head(const float* __restrict__ g2, const float* __restrict__ be2,
                       const float* __restrict__ Ws, const float* __restrict__ bs,
                       float* __restrict__ out) {
    __shared__ float p0sh[512];
    __shared__ float p1sh[512];
    int b = blockIdx.x, tid = threadIdx.x;
    float v = g_y2[b * C3n + tid];
    float z = fmaf(g2[tid] * (v - g_stats2[tid]), g_stats2[C3n + tid], be2[tid]);
    p0sh[tid] = z * Ws[tid];
    p1sh[tid] = z * Ws[C3n + tid];
    __syncthreads();
    for (int s = 256; s; s >>= 1) {
        if (tid < s) { p0sh[tid] += p0sh[tid + s]; p1sh[tid] += p1sh[tid + s]; }
        __syncthreads();
    }
    if (tid == 0) {
        float l0 = p0sh[0] + bs[0];
        float l1 = p1sh[0] + bs[1];
        float m = fmaxf(l0, l1);
        float lse = m + logf(expf(l0 - m) + expf(l1 - m));
        out[b * 2 + 0] = l0 - lse;
        out[b * 2 + 1] = l1 - lse;
    }
}

// ---------------- passthrough copies
__global__ void k_copy(const float* __restrict__ wp1, const float* __restrict__ wp2,
                       float* __restrict__ out) {
    int t = threadIdx.x;
    if (t < 32) out[OUT_WP1 + t] = wp1[t];
    else if (t < 64) out[OUT_WP2 + (t - 32)] = wp2[t - 32];
}

extern "C" void kernel_launch(void* const* d_in, const int* in_sizes, int n_in,
                              void* d_out, int out_size) {
    const float* x     = (const float*)d_in[0];
    const float* adj   = (const float*)d_in[1];
    const int*   roi   = (const int*)d_in[2];
    const float* W1a   = (const float*)d_in[3];
    const float* b1a   = (const float*)d_in[4];
    const float* W2a   = (const float*)d_in[5];
    const float* b2a   = (const float*)d_in[6];
    const float* bias1 = (const float*)d_in[7];
    const float* W1b   = (const float*)d_in[8];
    const float* b1b   = (const float*)d_in[9];
    const float* W2b   = (const float*)d_in[10];
    const float* b2b   = (const float*)d_in[11];
    const float* bias2 = (const float*)d_in[12];
    const float* wp1   = (const float*)d_in[13];
    const float* wp2   = (const float*)d_in[14];
    const float* Wm1   = (const float*)d_in[15];
    const float* bm1   = (const float*)d_in[16];
    const float* g1    = (const float*)d_in[17];
    const float* be1   = (const float*)d_in[18];
    const float* Wm2   = (const float*)d_in[19];
    const float* bm2   = (const float*)d_in[20];
    const float* g2    = (const float*)d_in[21];
    const float* be2   = (const float*)d_in[22];
    const float* Ws    = (const float*)d_in[23];
    const float* bs    = (const float*)d_in[24];
    float* out = (float*)d_out;

    k_tab<<<Rn, 256>>>(W1a, b1a, W2a, b2a, Rn * C1n, 0);
    k_tab<<<Rn, 256>>>(W1b, b1b, W2b, b2b, C1n * C2n, 1);
    k_xt1<<<dim3(Rn, 8), 256>>>(x, roi);
    k_att1<<<dim3(Bn, 25), 256>>>(adj, bias1, wp1);
    k_topk<<<Bn, 256>>>(0, out + OUT_S1);
    k_gather1<<<Bn, 256>>>(adj, roi);
    k_aug<<<dim3(Bn, 13), 256>>>();
    k_xt2<<<dim3(Bn, 13), 256>>>();
    k_att2<<<dim3(Bn, 4), 256>>>(bias2, wp2);
    k_topk<<<Bn, 256>>>(1, out + OUT_S2);
    k_feat<<<Bn, 256>>>(Wm1, bm1);
    k_bn<<<C2n, 512>>>(0);
    k_mlp2<<<Bn, C3n>>>(Wm2, bm2, g1, be1);
    k_bn<<<C3n, 512>>>(1);
    k_head<<<Bn, C3n>>>(g2, be2, Ws, bs, out);
    k_copy<<<1, 64>>>(wp1, wp2, out);
}

// round 13
// speedup vs baseline: 1.2590x; 1.0212x over previous
#include <cuda_runtime.h>
#include <math.h>

#define NEGF (-1000000000.0f)
#define Bn 512
#define Rn 200
#define C1n 32
#define C2n 32
#define C3n 512
#define KHn 8
#define K1n 100
#define K2n 50
#define FULLM 0xffffffffu

// out layout: logp[1024] | wp1[32] | wp2[32] | s1[512*100] | s2[512*50]
#define OUT_WP1 1024
#define OUT_WP2 1056
#define OUT_S1 1088
#define OUT_S2 52288

// ---------------- scratch ----------------
__device__ float g_wtab1[Rn * Rn * C1n];
__device__ float g_wtab2[Rn * C1n * C2n];
__device__ float g_xt1[Bn * Rn * C1n];
__device__ float g_h1[Bn * Rn * C1n];
__device__ float g_s1[Bn * Rn];
__device__ int   g_perm1[Bn * K1n];
__device__ float g_vals1[Bn * K1n];
__device__ int   g_roi1[Bn * K1n];
__device__ float g_x1[Bn * K1n * C1n];
__device__ float g_wd[Bn * K1n * K1n];
__device__ float g_aaug[Bn * K1n * K1n];
__device__ unsigned char g_maug[Bn * K1n * K1n];
__device__ float g_xt2[Bn * K1n * C2n];
__device__ float g_h2[Bn * K1n * C2n];
__device__ float g_s2[Bn * K1n];
__device__ int   g_perm2[Bn * K2n];
__device__ float g_vals2[Bn * K2n];
__device__ float g_y1[Bn * C2n];
__device__ float g_y2[Bn * C3n];
__device__ float g_stats1[2 * C2n];
__device__ float g_stats2[2 * C3n];

// ---------------- NN weight tables ----------------
__global__ void k_tab(const float* __restrict__ W1, const float* __restrict__ b1,
                      const float* __restrict__ W2, const float* __restrict__ b2,
                      int ncols, int which) {
    float* out = which ? g_wtab2 : g_wtab1;
    __shared__ float a[KHn];
    int r = blockIdx.x;
    if (threadIdx.x < KHn) {
        float v = W1[threadIdx.x * Rn + r] + b1[threadIdx.x];
        a[threadIdx.x] = v > 0.f ? v : 0.f;
    }
    __syncthreads();
    for (int j = threadIdx.x; j < ncols; j += blockDim.x) {
        float acc = b2[j];
#pragma unroll
        for (int k = 0; k < KHn; k++) acc = fmaf(a[k], W2[j * KHn + k], acc);
        out[(size_t)r * ncols + j] = acc;
    }
}

// ---------------- xt1[b,n,o] = sum_i x[b,n,i]*wtab1[roi[n]][i][o]
__global__ void k_xt1(const float* __restrict__ x, const int* __restrict__ roi) {
    __shared__ float Wsh[Rn * C1n];
    int n = blockIdx.x;
    int r = roi[n];
    const float* wsrc = g_wtab1 + (size_t)r * (Rn * C1n);
    for (int i = threadIdx.x; i < Rn * C1n; i += 256) Wsh[i] = wsrc[i];
    __syncthreads();
    int lane = threadIdx.x & 31, w = threadIdx.x >> 5;
    int b0 = blockIdx.y * 64 + w * 8;
    float acc[8];
#pragma unroll
    for (int k = 0; k < 8; k++) acc[k] = 0.f;
    const float* xb = x + (size_t)b0 * (Rn * Rn) + (size_t)n * Rn;
    for (int i0 = 0; i0 < Rn; i0 += 4) {
        float4 xv[8];
#pragma unroll
        for (int k = 0; k < 8; k++)
            xv[k] = *reinterpret_cast<const float4*>(&xb[(size_t)k * (Rn * Rn) + i0]);
#pragma unroll
        for (int d = 0; d < 4; d++) {
            float wv = Wsh[(i0 + d) * C1n + lane];
#pragma unroll
            for (int k = 0; k < 8; k++) {
                const float* xc = reinterpret_cast<const float*>(&xv[k]);
                acc[k] = fmaf(xc[d], wv, acc[k]);
            }
        }
    }
#pragma unroll
    for (int k = 0; k < 8; k++)
        g_xt1[(size_t)(b0 + k) * (Rn * C1n) + n * C1n + lane] = acc[k];
}

// ---------------- layer-1 attention, SPARSE with warp compaction.
// Row max is ALWAYS the diag logit 1.0 -> att_j = exp(a_j-1)/Z, Z = 1 + sum(e).
// Phase 1: ballot+popc compacts (e, j) pairs into shared (no per-edge shfl).
// Phase 2: short dense loop over compacted edges, 2 independent accumulators.
// grid (512, 25), block 256: one warp per row n, lane = channel o.
__global__ void k_att1(const float* __restrict__ adj, const float* __restrict__ bias1,
                       const float* __restrict__ wp1) {
    __shared__ float eSh[8][224];
    __shared__ int   jSh[8][224];
    int b = blockIdx.x;
    int lane = threadIdx.x & 31, w = threadIdx.x >> 5;
    int n = blockIdx.y * 8 + w;
    const float* arow = adj + ((size_t)b * Rn + n) * Rn;
    const float* xb = g_xt1 + (size_t)b * (Rn * C1n);

    unsigned lmask = (1u << lane) - 1u;
    int base = 0;
    float zpart = 0.f;
#pragma unroll
    for (int it = 0; it < 7; it++) {
        int j = it * 32 + lane;
        float a = (j < Rn) ? __ldg(&arow[j]) : 1.0f;
        bool isedge = (j < Rn) && (j != n) && (a < 0.1f);
        unsigned bits = __ballot_sync(FULLM, isedge);
        if (isedge) {
            float e = __expf(a - 1.0f);
            zpart += e;
            int pos = base + __popc(bits & lmask);
            eSh[w][pos] = e;
            jSh[w][pos] = j;
        }
        base += __popc(bits);
    }
    __syncwarp();

    float Z = zpart;
#pragma unroll
    for (int o = 16; o; o >>= 1) Z += __shfl_xor_sync(FULLM, Z, o);
    Z += 1.0f;  // diagonal: exp(1-1) = 1
    float invZ = 1.0f / Z;

    float acc0 = 0.f, acc1 = 0.f;
    int k = 0;
    for (; k + 1 < base; k += 2) {
        float e0 = eSh[w][k], e1 = eSh[w][k + 1];
        int j0 = jSh[w][k], j1 = jSh[w][k + 1];
        acc0 = fmaf(e0, __ldg(&xb[j0 * C1n + lane]), acc0);
        acc1 = fmaf(e1, __ldg(&xb[j1 * C1n + lane]), acc1);
    }
    if (k < base)
        acc0 = fmaf(eSh[w][k], __ldg(&xb[jSh[w][k] * C1n + lane]), acc0);
    float acc = acc0 + acc1;

    float h = fmaf(acc + __ldg(&xb[n * C1n + lane]), invZ, bias1[lane]);
    g_h1[((size_t)b * Rn + n) * C1n + lane] = h;

    float wv = wp1[lane];
    float t = h * wv;
    float wn = wv * wv;
#pragma unroll
    for (int o = 16; o; o >>= 1) {
        t += __shfl_xor_sync(FULLM, t, o);
        wn += __shfl_xor_sync(FULLM, wn, o);
    }
    if (lane == 0) {
        float norm = sqrtf(wn);
        g_s1[b * Rn + n] = 1.f / (1.f + __expf(-(t / norm)));
    }
}

// ---------------- exact stable top-k by rank (matches lax.top_k tie semantics)
__global__ void k_topk(int stage, float* __restrict__ outp) {
    const float* s; int N, Ksel; int* perm; float* vals;
    if (stage == 0) { s = g_s1; N = Rn;  Ksel = K1n; perm = g_perm1; vals = g_vals1; }
    else            { s = g_s2; N = K1n; Ksel = K2n; perm = g_perm2; vals = g_vals2; }
    __shared__ float sv[256];
    int b = blockIdx.x, tid = threadIdx.x;
    sv[tid] = (tid < N) ? s[b * N + tid] : -INFINITY;
    __syncthreads();
    if (tid < N) {
        float v = sv[tid];
        int rank = 0;
        for (int j = 0; j < N; j++) {
            float u = sv[j];
            rank += (u > v) || (u == v && j < tid);
        }
        if (rank < Ksel) {
            perm[b * Ksel + rank] = tid;
            vals[b * Ksel + rank] = v;
            outp[b * Ksel + rank] = 1.f / (1.f + __expf(-v));  // sigmoid(vals)
        }
    }
}

// ---------------- gather x1, roi1; build wd (diag 1, masked adj else 0)
__global__ void k_gather1(const float* __restrict__ adj, const int* __restrict__ roi) {
    __shared__ int permsh[K1n];
    __shared__ float valsh[K1n];
    int b = blockIdx.x, tid = threadIdx.x;
    if (tid < K1n) {
        int p = g_perm1[b * K1n + tid];
        permsh[tid] = p;
        valsh[tid] = g_vals1[b * K1n + tid];
        g_roi1[b * K1n + tid] = roi[p];
    }
    __syncthreads();
    for (int idx = tid; idx < K1n * C1n; idx += 256) {
        int p = idx >> 5, o = idx & 31;
        g_x1[(size_t)b * (K1n * C1n) + idx] =
            g_h1[((size_t)b * Rn + permsh[p]) * C1n + o] * valsh[p];
    }
    for (int idx = tid; idx < K1n * K1n; idx += 256) {
        int i = idx / K1n, k = idx - i * K1n;
        float outv;
        if (i == k) outv = 1.0f;
        else {
            float a = adj[((size_t)b * Rn + permsh[i]) * Rn + permsh[k]];
            outv = (a < 0.1f) ? a : 0.0f;
        }
        g_wd[(size_t)b * (K1n * K1n) + idx] = outv;
    }
}

// ---------------- a2 = wd@wd SPARSE (wd rows ~11/100 nonzero, incl. diag).
__global__ void k_aug() {
    int b = blockIdx.x;
    int lane = threadIdx.x & 31, w = threadIdx.x >> 5;
    int i = blockIdx.y * 8 + w;
    if (i >= K1n) return;
    const float* wdb = g_wd + (size_t)b * (K1n * K1n);
    const float* ri = wdb + i * K1n;
    float r[4];
    float acc[4] = {0.f, 0.f, 0.f, 0.f};
#pragma unroll
    for (int c = 0; c < 4; c++) {
        int j = c * 32 + lane;
        r[c] = (j < K1n) ? __ldg(&ri[j]) : 0.f;
    }
#pragma unroll
    for (int c = 0; c < 4; c++) {
        unsigned bits = __ballot_sync(FULLM, r[c] != 0.f);
        while (bits) {
            int src = __ffs(bits) - 1;
            bits &= bits - 1;
            float wik = __shfl_sync(FULLM, r[c], src);
            int k = c * 32 + src;
            const float* rk = wdb + k * K1n;
#pragma unroll
            for (int cc = 0; cc < 4; cc++) {
                int j = cc * 32 + lane;
                if (j < K1n) acc[cc] = fmaf(wik, __ldg(&rk[j]), acc[cc]);
            }
        }
    }
#pragma unroll
    for (int cc = 0; cc < 4; cc++) {
        int j = cc * 32 + lane;
        if (j < K1n) {
            float v = acc[cc];
            bool diag = (j == i);
            g_aaug[(size_t)b * (K1n * K1n) + i * K1n + j] = diag ? 0.f : v;
            g_maug[(size_t)b * (K1n * K1n) + i * K1n + j] =
                (!diag && v != 0.f) ? (unsigned char)1 : (unsigned char)0;
        }
    }
}

// ---------------- xt2[b,p,o] = sum_i x1[b,p,i]*wtab2[roi1[b,p]][i][o]
__global__ void k_xt2() {
    int b = blockIdx.x;
    int lane = threadIdx.x & 31, w = threadIdx.x >> 5;
    int p = blockIdx.y * 8 + w;
    if (p >= K1n) return;
    int r = g_roi1[b * K1n + p];
    const float* xr = g_x1 + ((size_t)b * K1n + p) * C1n;
    const float* wt = g_wtab2 + (size_t)r * (C1n * C2n);
    float acc = 0.f;
#pragma unroll
    for (int i = 0; i < C1n; i++) acc = fmaf(__ldg(&xr[i]), __ldg(&wt[i * C2n + lane]), acc);
    g_xt2[((size_t)b * K1n + p) * C2n + lane] = acc;
}

// ---------------- layer-2 attention + h2 + score s2. grid (512, 4), block 256.
__global__ void k_att2(const float* __restrict__ bias2, const float* __restrict__ wp2) {
    __shared__ float xtsh[K1n * C2n];
    __shared__ __align__(16) float attsh[K1n * 36];
    __shared__ float rowscale[32];
    int b = blockIdx.x;
    int n0 = blockIdx.y * 32;
    int tid = threadIdx.x, lane = tid & 31, w = tid >> 5;
    const float* xb = g_xt2 + (size_t)b * (K1n * C2n);
    for (int i = tid; i < K1n * C2n; i += 256) xtsh[i] = xb[i];
    const float* ab = g_aaug + (size_t)b * (K1n * K1n);
    const unsigned char* mb = g_maug + (size_t)b * (K1n * K1n);

#pragma unroll
    for (int rr = 0; rr < 4; rr++) {
        int rloc = w * 4 + rr;
        int n = n0 + rloc;
        if (n < K1n) {
            float lv[4];
            float m = -INFINITY;
#pragma unroll
            for (int it = 0; it < 4; it++) {
                int j = lane + it * 32;
                float l = -INFINITY;
                if (j < K1n)
                    l = (j == n) ? 1.0f : (mb[n * K1n + j] ? ab[n * K1n + j] : NEGF);
                lv[it] = l;
                m = fmaxf(m, l);
            }
#pragma unroll
            for (int o = 16; o; o >>= 1) m = fmaxf(m, __shfl_xor_sync(FULLM, m, o));
            float s = 0.f;
#pragma unroll
            for (int it = 0; it < 4; it++) {
                int j = lane + it * 32;
                if (j < K1n) {
                    float e = __expf(lv[it] - m);
                    attsh[j * 36 + rloc] = e;
                    s += e;
                }
            }
#pragma unroll
            for (int o = 16; o; o >>= 1) s += __shfl_xor_sync(FULLM, s, o);
            if (lane == 0) rowscale[rloc] = 1.0f / s;
        } else {
#pragma unroll
            for (int it = 0; it < 4; it++) {
                int j = lane + it * 32;
                if (j < K1n) attsh[j * 36 + rloc] = 0.f;
            }
        }
    }
    __syncthreads();

    float a0 = 0.f, a1 = 0.f, a2 = 0.f, a3 = 0.f;
    int o = lane;
    for (int j = 0; j < K1n; j++) {
        float xv = xtsh[j * C2n + o];
        float4 av = *reinterpret_cast<const float4*>(&attsh[j * 36 + w * 4]);
        a0 = fmaf(av.x, xv, a0);
        a1 = fmaf(av.y, xv, a1);
        a2 = fmaf(av.z, xv, a2);
        a3 = fmaf(av.w, xv, a3);
    }
    float bo = bias2[o];
    float wv = wp2[o];
    float wn = 0.f;
#pragma unroll
    for (int i = 0; i < C2n; i++) { float t = wp2[i]; wn = fmaf(t, t, wn); }
    float norm = sqrtf(wn);
    float accs[4] = {a0, a1, a2, a3};
#pragma unroll
    for (int rr = 0; rr < 4; rr++) {
        int rloc = w * 4 + rr;
        int n = n0 + rloc;
        if (n < K1n) {
            float h = fmaf(accs[rr], rowscale[rloc], bo);
            g_h2[((size_t)b * K1n + n) * C2n + o] = h;
            float t = h * wv;
#pragma unroll
            for (int off = 16; off; off >>= 1) t += __shfl_xor_sync(FULLM, t, off);
            if (lane == 0) g_s2[b * K1n + n] = 1.f / (1.f + __expf(-(t / norm)));
        }
    }
}

// ---------------- feature concat + MLP layer 1 (pre-BN, post-leaky)
__global__ void k_feat(const float* __restrict__ Wm1, const float* __restrict__ bm1) {
    __shared__ float red[8 * 32];
    __shared__ float red2[8 * 32];
    __shared__ float featsh[128];
    int b = blockIdx.x, tid = threadIdx.x, lane = tid & 31, w = tid >> 5;

    const float* x1b = g_x1 + (size_t)b * (K1n * C1n);
    float mx = -INFINITY, sm = 0.f;
    for (int p = w; p < K1n; p += 8) {
        float v = x1b[p * C1n + lane];
        mx = fmaxf(mx, v);
        sm += v;
    }
    red[w * 32 + lane] = mx;
    red2[w * 32 + lane] = sm;
    __syncthreads();
    if (w == 0) {
        float m = red[lane], s = red2[lane];
#pragma unroll
        for (int q = 1; q < 8; q++) { m = fmaxf(m, red[q * 32 + lane]); s += red2[q * 32 + lane]; }
        featsh[lane] = m;
        featsh[32 + lane] = s / (float)K1n;
    }
    __syncthreads();

    const float* h2b = g_h2 + (size_t)b * (K1n * C2n);
    mx = -INFINITY;
    sm = 0.f;
    for (int p = w; p < K2n; p += 8) {
        int pp = g_perm2[b * K2n + p];
        float v = h2b[pp * C2n + lane] * g_vals2[b * K2n + p];
        mx = fmaxf(mx, v);
        sm += v;
    }
    red[w * 32 + lane] = mx;
    red2[w * 32 + lane] = sm;
    __syncthreads();
    if (w == 0) {
        float m = red[lane], s = red2[lane];
#pragma unroll
        for (int q = 1; q < 8; q++) { m = fmaxf(m, red[q * 32 + lane]); s += red2[q * 32 + lane]; }
        featsh[64 + lane] = m;
        featsh[96 + lane] = s / (float)K2n;
    }
    __syncthreads();

    if (tid < C2n) {
        float acc = bm1[tid];
        const float* wrow = Wm1 + tid * 128;
#pragma unroll
        for (int f = 0; f < 128; f++) acc = fmaf(featsh[f], wrow[f], acc);
        g_y1[b * C2n + tid] = acc > 0.f ? acc : 0.01f * acc;
    }
}

// ---------------- batch-norm stats (two-pass). block=512 (one thread per row).
__global__ void k_bn(int stage) {
    const float* y = stage ? g_y2 : g_y1;
    int ncols = stage ? C3n : C2n;
    float* stats = stage ? g_stats2 : g_stats1;
    __shared__ float sh[512];
    __shared__ float mu_s;
    int c = blockIdx.x, tid = threadIdx.x;
    float v = y[(size_t)tid * ncols + c];
    sh[tid] = v;
    __syncthreads();
    for (int s = 256; s; s >>= 1) {
        if (tid < s) sh[tid] += sh[tid + s];
        __syncthreads();
    }
    if (tid == 0) mu_s = sh[0] * (1.0f / 512.0f);
    __syncthreads();
    float d = v - mu_s;
    sh[tid] = d * d;
    __syncthreads();
    for (int s = 256; s; s >>= 1) {
        if (tid < s) sh[tid] += sh[tid + s];
        __syncthreads();
    }
    if (tid == 0) {
        stats[c] = mu_s;
        stats[ncols + c] = rsqrtf(sh[0] * (1.0f / 512.0f) + 1e-5f);
    }
}

// ---------------- MLP layer 2
__global__ void k_mlp2(const float* __restrict__ Wm2, const float* __restrict__ bm2,
                       const float* __restrict__ g1, const float* __restrict__ be1) {
    __shared__ float ynorm[C2n];
    int b = blockIdx.x, tid = threadIdx.x;
    if (tid < C2n) {
        float v = g_y1[b * C2n + tid];
        ynorm[tid] = fmaf(g1[tid] * (v - g_stats1[tid]), g_stats1[C2n + tid], be1[tid]);
    }
    __syncthreads();
    float acc = bm2[tid];
    const float* wrow = Wm2 + tid * C2n;
#pragma unroll
    for (int i = 0; i < C2n; i++) acc = fmaf(ynorm[i], wrow[i], acc);
    g_y2[b * C3n + tid] = acc > 0.f ? acc : 0.01f * acc;
}

// ---------------- head
__global__ void k_head(const float* __restrict__ g2, const float* __restrict__ be2,
                       const float* __restrict__ Ws, const float* __restrict__ bs,
                       float* __restrict__ out) {
    __shared__ float p0sh[512];
    __shared__ float p1sh[512];
    int b = blockIdx.x, tid = threadIdx.x;
    float v = g_y2[b * C3n + tid];
    float z = fmaf(g2[tid] * (v - g_stats2[tid]), g_stats2[C3n + tid], be2[tid]);
    p0sh[tid] = z * Ws[tid];
    p1sh[tid] = z * Ws[C3n + tid];
    __syncthreads();
    for (int s = 256; s; s >>= 1) {
        if (tid < s) { p0sh[tid] += p0sh[tid + s]; p1sh[tid] += p1sh[tid + s]; }
        __syncthreads();
    }
    if (tid == 0) {
        float l0 = p0sh[0] + bs[0];
        float l1 = p1sh[0] + bs[1];
        float m = fmaxf(l0, l1);
        float lse = m + logf(expf(l0 - m) + expf(l1 - m));
        out[b * 2 + 0] = l0 - lse;
        out[b * 2 + 1] = l1 - lse;
    }
}

// ---------------- passthrough copies
__global__ void k_copy(const float* __restrict__ wp1, const float* __restrict__ wp2,
                       float* __restrict__ out) {
    int t = threadIdx.x;
    if (t < 32) out[OUT_WP1 + t] = wp1[t];
    else if (t < 64) out[OUT_WP2 + (t - 32)] = wp2[t - 32];
}

extern "C" void kernel_launch(void* const* d_in, const int* in_sizes, int n_in,
                              void* d_out, int out_size) {
    const float* x     = (const float*)d_in[0];
    const float* adj   = (const float*)d_in[1];
    const int*   roi   = (const int*)d_in[2];
    const float* W1a   = (const float*)d_in[3];
    const float* b1a   = (const float*)d_in[4];
    const float* W2a   = (const float*)d_in[5];
    const float* b2a   = (const float*)d_in[6];
    const float* bias1 = (const float*)d_in[7];
    const float* W1b   = (const float*)d_in[8];
    const float* b1b   = (const float*)d_in[9];
    const float* W2b   = (const float*)d_in[10];
    const float* b2b   = (const float*)d_in[11];
    const float* bias2 = (const float*)d_in[12];
    const float* wp1   = (const float*)d_in[13];
    const float* wp2   = (const float*)d_in[14];
    const float* Wm1   = (const float*)d_in[15];
    const float* bm1   = (const float*)d_in[16];
    const float* g1    = (const float*)d_in[17];
    const float* be1   = (const float*)d_in[18];
    const float* Wm2   = (const float*)d_in[19];
    const float* bm2   = (const float*)d_in[20];
    const float* g2    = (const float*)d_in[21];
    const float* be2   = (const float*)d_in[22];
    const float* Ws    = (const float*)d_in[23];
    const float* bs    = (const float*)d_in[24];
    float* out = (float*)d_out;

    k_tab<<<Rn, 256>>>(W1a, b1a, W2a, b2a, Rn * C1n, 0);
    k_tab<<<Rn, 256>>>(W1b, b1b, W2b, b2b, C1n * C2n, 1);
    k_xt1<<<dim3(Rn, 8), 256>>>(x, roi);
    k_att1<<<dim3(Bn, 25), 256>>>(adj, bias1, wp1);
    k_topk<<<Bn, 256>>>(0, out + OUT_S1);
    k_gather1<<<Bn, 256>>>(adj, roi);
    k_aug<<<dim3(Bn, 13), 256>>>();
    k_xt2<<<dim3(Bn, 13), 256>>>();
    k_att2<<<dim3(Bn, 4), 256>>>(bias2, wp2);
    k_topk<<<Bn, 256>>>(1, out + OUT_S2);
    k_feat<<<Bn, 256>>>(Wm1, bm1);
    k_bn<<<C2n, 512>>>(0);
    k_mlp2<<<Bn, C3n>>>(Wm2, bm2, g1, be1);
    k_bn<<<C3n, 512>>>(1);
    k_head<<<Bn, C3n>>>(g2, be2, Ws, bs, out);
    k_copy<<<1, 64>>>(wp1, wp2, out);
}